// round 1
// baseline (speedup 1.0000x reference)
#include <cuda_runtime.h>
#include <math.h>

#define NN   50000
#define DD   16
#define FF   128
#define F4   512
#define CCLS 40

// ---- scratch (device globals: allocation-free rule) ----
__device__ float g_xp[(size_t)NN * FF];     // 25.6 MB  projected features
__device__ float g_G[(size_t)NN * F4];      // 102.4 MB precomputed gate inputs (fits L2)
__device__ float g_aggr[(size_t)NN * FF];   // 25.6 MB  LSTM aggregation output
__device__ float g_h1[(size_t)NN * FF];     // 25.6 MB  layer-1 output

// ============================================================================
// Generic tiled fp32 GEMM: C = act( A[M,K=128] @ W[Nout,128]^T (+ A2@W2^T) + b (+ b2) )
// BM=BN=64, BK=16, 256 threads, 4x4 micro-tile.
// ============================================================================
template<bool RELU, bool DUAL, bool HASB2>
__global__ __launch_bounds__(256) void gemm_kernel(
    const float* __restrict__ A,  const float* __restrict__ W,
    const float* __restrict__ A2, const float* __restrict__ W2,
    const float* __restrict__ bias, const float* __restrict__ bias2,
    float* __restrict__ C, int M, int Nout)
{
    __shared__ float As[16][65];
    __shared__ float Ws[16][65];
    const int tid = threadIdx.x;
    const int tx = tid & 15, ty = tid >> 4;
    const int rowBase = blockIdx.y * 64;
    const int colBase = blockIdx.x * 64;
    const int lk = tid & 15, lr = tid >> 4;

    float acc[4][4] = {};

    const int npass = DUAL ? 2 : 1;
    for (int p = 0; p < npass; p++) {
        const float* Ap = p ? A2 : A;
        const float* Wp = p ? W2 : W;
        for (int k0 = 0; k0 < FF; k0 += 16) {
            #pragma unroll
            for (int r = 0; r < 4; r++) {
                int row = rowBase + lr + r * 16;
                As[lk][lr + r * 16] = (row < M) ? Ap[(size_t)row * FF + k0 + lk] : 0.f;
                int wr = colBase + lr + r * 16;
                Ws[lk][lr + r * 16] = (wr < Nout) ? Wp[(size_t)wr * FF + k0 + lk] : 0.f;
            }
            __syncthreads();
            #pragma unroll
            for (int kk = 0; kk < 16; kk++) {
                float a[4], b[4];
                #pragma unroll
                for (int i = 0; i < 4; i++) a[i] = As[kk][ty * 4 + i];
                #pragma unroll
                for (int j = 0; j < 4; j++) b[j] = Ws[kk][tx * 4 + j];
                #pragma unroll
                for (int i = 0; i < 4; i++)
                    #pragma unroll
                    for (int j = 0; j < 4; j++)
                        acc[i][j] = fmaf(a[i], b[j], acc[i][j]);
            }
            __syncthreads();
        }
    }

    #pragma unroll
    for (int i = 0; i < 4; i++) {
        int row = rowBase + ty * 4 + i;
        if (row >= M) continue;
        #pragma unroll
        for (int j = 0; j < 4; j++) {
            int col = colBase + tx * 4 + j;
            if (col >= Nout) continue;
            float v = acc[i][j] + bias[col];
            if (HASB2) v += bias2[col];
            if (RELU)  v = fmaxf(v, 0.f);
            C[(size_t)row * Nout + col] = v;
        }
    }
}

// ============================================================================
// LSTM aggregation kernel.
// CTA = 64 nodes, 256 threads. thread(tx,ty): tx in [0,16) -> 8 hidden units,
// ty in [0,16) -> 4 nodes. All 4 gates for the same hidden units kept in
// registers (acc[node][gate][unit] = 128 accumulators), c fully register
// resident, h round-trips through SMEM each step.
// Per step: acc init from gathered G rows (L2-resident), then h @ Whh^T via
// SMEM-staged Whh k-chunks ([16 x 512] transposed, padded to 516).
// ============================================================================
__global__ __launch_bounds__(256, 1) void lstm_kernel(
    const float* __restrict__ G,    // [N, 512]
    const int*   __restrict__ esrc, // [N, 16]
    const float* __restrict__ Whh,  // [512, 128]
    float*       __restrict__ aggr) // [N, 128]
{
    extern __shared__ float smem[];
    float (*h_s)[FF]  = reinterpret_cast<float (*)[FF]>(smem);            // 64x128
    float (*w_s)[516] = reinterpret_cast<float (*)[516]>(smem + 64 * FF); // 16x516

    const int tid = threadIdx.x;
    const int tx = tid & 15;     // unit group: units tx*8 .. tx*8+7
    const int ty = tid >> 4;     // node group: nodes ty*4 .. ty*4+3
    const int nodeBase = blockIdx.x * 64;

    float c_reg[4][8];
    #pragma unroll
    for (int i = 0; i < 4; i++)
        #pragma unroll
        for (int j = 0; j < 8; j++) c_reg[i][j] = 0.f;

    float acc[4][4][8];  // [node][gate][unit]

    for (int i = tid; i < 64 * FF; i += 256) smem[i] = 0.f;
    __syncthreads();

    for (int t = 0; t < 16; t++) {
        // ---- init accumulators from gathered G rows (gate bias already folded in) ----
        #pragma unroll
        for (int i = 0; i < 4; i++) {
            int n = nodeBase + ty * 4 + i;
            int src = (n < NN) ? esrc[n * DD + t] : 0;
            const float* gr = G + (size_t)src * F4;
            #pragma unroll
            for (int g = 0; g < 4; g++) {
                float4 v0 = *reinterpret_cast<const float4*>(gr + g * FF + tx * 8);
                float4 v1 = *reinterpret_cast<const float4*>(gr + g * FF + tx * 8 + 4);
                acc[i][g][0] = v0.x; acc[i][g][1] = v0.y; acc[i][g][2] = v0.z; acc[i][g][3] = v0.w;
                acc[i][g][4] = v1.x; acc[i][g][5] = v1.y; acc[i][g][6] = v1.z; acc[i][g][7] = v1.w;
            }
        }

        // ---- recurrent GEMM: acc += h @ Whh^T (skip at t=0 since h=0) ----
        if (t > 0) {
            for (int k0 = 0; k0 < FF; k0 += 16) {
                {   // stage Whh[:, k0:k0+16] transposed into SMEM
                    const int lk = tid & 15;
                    const int ug = tid >> 4;
                    #pragma unroll
                    for (int r = 0; r < 32; r++) {
                        int u = ug + r * 16;
                        w_s[lk][u] = Whh[u * FF + k0 + lk];
                    }
                }
                __syncthreads();
                #pragma unroll
                for (int kk = 0; kk < 16; kk++) {
                    float a0 = h_s[ty * 4 + 0][k0 + kk];
                    float a1 = h_s[ty * 4 + 1][k0 + kk];
                    float a2 = h_s[ty * 4 + 2][k0 + kk];
                    float a3 = h_s[ty * 4 + 3][k0 + kk];
                    #pragma unroll
                    for (int g = 0; g < 4; g++) {
                        const float* wr = &w_s[kk][g * FF + tx * 8];
                        float4 b0 = *reinterpret_cast<const float4*>(wr);
                        float4 b1 = *reinterpret_cast<const float4*>(wr + 4);
                        float bb[8] = {b0.x, b0.y, b0.z, b0.w, b1.x, b1.y, b1.z, b1.w};
                        #pragma unroll
                        for (int j = 0; j < 8; j++) {
                            acc[0][g][j] = fmaf(a0, bb[j], acc[0][g][j]);
                            acc[1][g][j] = fmaf(a1, bb[j], acc[1][g][j]);
                            acc[2][g][j] = fmaf(a2, bb[j], acc[2][g][j]);
                            acc[3][g][j] = fmaf(a3, bb[j], acc[3][g][j]);
                        }
                    }
                }
                __syncthreads();
            }
        }

        // ---- elementwise gate update (c in registers, h written to SMEM) ----
        #pragma unroll
        for (int i = 0; i < 4; i++) {
            #pragma unroll
            for (int j = 0; j < 8; j++) {
                float iv = acc[i][0][j];
                float fv = acc[i][1][j];
                float gv = acc[i][2][j];
                float ov = acc[i][3][j];
                float ig = 1.f / (1.f + __expf(-iv));
                float fg = 1.f / (1.f + __expf(-fv));
                float gt = tanhf(gv);
                float cn = fg * c_reg[i][j] + ig * gt;
                c_reg[i][j] = cn;
                float og = 1.f / (1.f + __expf(-ov));
                h_s[ty * 4 + i][tx * 8 + j] = og * tanhf(cn);
            }
        }
        __syncthreads();
    }

    // ---- final h = LSTM aggregation output ----
    #pragma unroll
    for (int i = 0; i < 4; i++) {
        int n = nodeBase + ty * 4 + i;
        if (n < NN) {
            *reinterpret_cast<float4*>(aggr + (size_t)n * FF + tx * 8) =
                *reinterpret_cast<const float4*>(&h_s[ty * 4 + i][tx * 8]);
            *reinterpret_cast<float4*>(aggr + (size_t)n * FF + tx * 8 + 4) =
                *reinterpret_cast<const float4*>(&h_s[ty * 4 + i][tx * 8 + 4]);
        }
    }
}

// ============================================================================
extern "C" void kernel_launch(void* const* d_in, const int* in_sizes, int n_in,
                              void* d_out, int out_size)
{
    const float* x    = (const float*)d_in[0];
    const int*   esrc = (const int*)d_in[1];
    // d_in[2..7] = dead MLP branch (W1,b1,W2,b2,W3,b3) — unused by the output.
    const float* Wp1  = (const float*)d_in[8];
    const float* bp1  = (const float*)d_in[9];
    const float* Wih1 = (const float*)d_in[10];
    const float* Whh1 = (const float*)d_in[11];
    const float* bih1 = (const float*)d_in[12];
    const float* bhh1 = (const float*)d_in[13];
    const float* Wl1  = (const float*)d_in[14];
    const float* bl1  = (const float*)d_in[15];
    const float* Wr1  = (const float*)d_in[16];
    const float* Wp2  = (const float*)d_in[17];
    const float* bp2  = (const float*)d_in[18];
    const float* Wih2 = (const float*)d_in[19];
    const float* Whh2 = (const float*)d_in[20];
    const float* bih2 = (const float*)d_in[21];
    const float* bhh2 = (const float*)d_in[22];
    const float* Wl2  = (const float*)d_in[23];
    const float* bl2  = (const float*)d_in[24];
    const float* Wr2  = (const float*)d_in[25];
    float* out = (float*)d_out;

    float *xp, *G, *aggr, *h1;
    cudaGetSymbolAddress((void**)&xp,   g_xp);
    cudaGetSymbolAddress((void**)&G,    g_G);
    cudaGetSymbolAddress((void**)&aggr, g_aggr);
    cudaGetSymbolAddress((void**)&h1,   g_h1);

    const int lstmSmem = (64 * FF + 16 * 516) * (int)sizeof(float);  // 65792 B
    cudaFuncSetAttribute(lstm_kernel, cudaFuncAttributeMaxDynamicSharedMemorySize, lstmSmem);

    dim3 thr(256);
    const int mblk = (NN + 63) / 64;      // 782
    dim3 gN128(2, mblk);                  // Nout=128
    dim3 gN512(8, mblk);                  // Nout=512
    dim3 gN40(1, mblk);                   // Nout=40

    // ---------- layer 1 ----------
    gemm_kernel<true, false, false><<<gN128, thr>>>(x, Wp1, nullptr, nullptr, bp1, nullptr, xp, NN, FF);
    gemm_kernel<false, false, true><<<gN512, thr>>>(xp, Wih1, nullptr, nullptr, bih1, bhh1, G, NN, F4);
    lstm_kernel<<<mblk, thr, lstmSmem>>>(G, esrc, Whh1, aggr);
    gemm_kernel<true, true, false><<<gN128, thr>>>(aggr, Wl1, x, Wr1, bl1, nullptr, h1, NN, FF);

    // ---------- layer 2 ----------
    gemm_kernel<true, false, false><<<gN128, thr>>>(h1, Wp2, nullptr, nullptr, bp2, nullptr, xp, NN, FF);
    gemm_kernel<false, false, true><<<gN512, thr>>>(xp, Wih2, nullptr, nullptr, bih2, bhh2, G, NN, F4);
    lstm_kernel<<<mblk, thr, lstmSmem>>>(G, esrc, Whh2, aggr);
    gemm_kernel<false, true, false><<<gN40, thr>>>(aggr, Wl2, h1, Wr2, bl2, nullptr, out, NN, CCLS);
}

// round 3
// speedup vs baseline: 5.4190x; 5.4190x over previous
#include <cuda_runtime.h>
#include <cuda_fp16.h>
#include <math.h>
#include <stdint.h>

#define NN   50000
#define DD   16
#define FF   128
#define F4   512
#define CCLS 40

// ---- scratch (device globals: allocation-free rule) ----
__device__ float  g_xp[(size_t)NN * FF];     // projected features fp32
__device__ __half g_G[(size_t)NN * F4];      // permuted gate preacts, fp16 (51MB, L2-resident)
__device__ float  g_aggr[(size_t)NN * FF];   // LSTM output
__device__ float  g_h1[(size_t)NN * FF];     // layer-1 output
__device__ __half g_Whhp[F4 * FF];           // permuted Whh fp16
__device__ __half g_Wihp[F4 * FF];           // permuted Wih fp16
__device__ float  g_biasp[F4];               // permuted bih+bhh

// ============================================================================
// helpers
// ============================================================================
__device__ __forceinline__ uint32_t smem_u32(const void* p) {
    uint32_t a;
    asm("{ .reg .u64 t; cvta.to.shared.u64 t, %1; cvt.u32.u64 %0, t; }" : "=r"(a) : "l"(p));
    return a;
}
__device__ __forceinline__ void ldsm4(uint32_t addr, uint32_t r[4]) {
    asm volatile("ldmatrix.sync.aligned.m8n8.x4.shared.b16 {%0,%1,%2,%3}, [%4];"
        : "=r"(r[0]), "=r"(r[1]), "=r"(r[2]), "=r"(r[3]) : "r"(addr));
}
__device__ __forceinline__ void mma16816(float d[4], const uint32_t a[4], uint32_t b0, uint32_t b1) {
    asm volatile("mma.sync.aligned.m16n8k16.row.col.f32.f16.f16.f32 "
        "{%0,%1,%2,%3},{%4,%5,%6,%7},{%8,%9},{%0,%1,%2,%3};"
        : "+f"(d[0]), "+f"(d[1]), "+f"(d[2]), "+f"(d[3])
        : "r"(a[0]), "r"(a[1]), "r"(a[2]), "r"(a[3]), "r"(b0), "r"(b1));
}
__device__ __forceinline__ float tna(float x) { float y; asm("tanh.approx.f32 %0, %1;" : "=f"(y) : "f"(x)); return y; }
__device__ __forceinline__ float sigf(float x) { return 0.5f + 0.5f * tna(0.5f * x); }
__device__ __forceinline__ float tanha(float x) {
    x = fminf(fmaxf(x, -10.f), 10.f);
    float e = __expf(2.f * x);
    return __fdividef(e - 1.f, e + 1.f);
}

// ============================================================================
// Gate-interleave permutation.
// Block nb = u/16; uu = u%16; a = uu/4; q = uu%4.
// P(u, i) = nb*64 + 16a + 2q ;  f: +1 ;  g: +8 ;  o: +9.
// In the m16n8k16 C layout (thread lane: q = lane%4, r = lane/4), the
// fragment cols {2q,2q+1} of tiles s=2a (i,f) and s=2a+1 (g,o) give one
// thread all 4 gates of unit u = nb*16+4a+q.
// ============================================================================
__global__ void prep_permute(const float* __restrict__ Wih, const float* __restrict__ Whh,
                             const float* __restrict__ bih, const float* __restrict__ bhh) {
    int p = blockIdx.x;                 // 0..511 permuted row
    int c = p & 63;
    int nb = p >> 6;
    int c15 = c & 15;
    int g = 2 * ((c15 >> 3) & 1) + (c15 & 1);
    int q = (c15 & 7) >> 1;
    int a = (c >> 4) & 3;
    int u = nb * 16 + 4 * a + q;
    int srow = g * FF + u;              // torch gate order i,f,g,o blocks of 128
    for (int k = threadIdx.x; k < FF; k += blockDim.x) {
        g_Wihp[p * FF + k] = __float2half_rn(Wih[srow * FF + k]);
        g_Whhp[p * FF + k] = __float2half_rn(Whh[srow * FF + k]);
    }
    if (threadIdx.x == 0) g_biasp[p] = bih[srow] + bhh[srow];
}

// ============================================================================
// fp32 SIMT GEMM (small layers): C = act( A@W^T (+ A2@W2^T) + b )
// ============================================================================
template<bool RELU, bool DUAL>
__global__ __launch_bounds__(256) void gemm_kernel(
    const float* __restrict__ A,  const float* __restrict__ W,
    const float* __restrict__ A2, const float* __restrict__ W2,
    const float* __restrict__ bias,
    float* __restrict__ C, int M, int Nout)
{
    __shared__ float As[16][65];
    __shared__ float Ws[16][65];
    const int tid = threadIdx.x;
    const int tx = tid & 15, ty = tid >> 4;
    const int rowBase = blockIdx.y * 64;
    const int colBase = blockIdx.x * 64;
    const int lk = tid & 15, lr = tid >> 4;
    float acc[4][4] = {};
    const int npass = DUAL ? 2 : 1;
    for (int p = 0; p < npass; p++) {
        const float* Ap = p ? A2 : A;
        const float* Wp = p ? W2 : W;
        for (int k0 = 0; k0 < FF; k0 += 16) {
            #pragma unroll
            for (int rr = 0; rr < 4; rr++) {
                int row = rowBase + lr + rr * 16;
                As[lk][lr + rr * 16] = (row < M) ? Ap[(size_t)row * FF + k0 + lk] : 0.f;
                int wr = colBase + lr + rr * 16;
                Ws[lk][lr + rr * 16] = (wr < Nout) ? Wp[(size_t)wr * FF + k0 + lk] : 0.f;
            }
            __syncthreads();
            #pragma unroll
            for (int kk = 0; kk < 16; kk++) {
                float av[4], bv[4];
                #pragma unroll
                for (int i = 0; i < 4; i++) av[i] = As[kk][ty * 4 + i];
                #pragma unroll
                for (int jj = 0; jj < 4; jj++) bv[jj] = Ws[kk][tx * 4 + jj];
                #pragma unroll
                for (int i = 0; i < 4; i++)
                    #pragma unroll
                    for (int jj = 0; jj < 4; jj++)
                        acc[i][jj] = fmaf(av[i], bv[jj], acc[i][jj]);
            }
            __syncthreads();
        }
    }
    #pragma unroll
    for (int i = 0; i < 4; i++) {
        int row = rowBase + ty * 4 + i;
        if (row >= M) continue;
        #pragma unroll
        for (int jj = 0; jj < 4; jj++) {
            int col = colBase + tx * 4 + jj;
            if (col >= Nout) continue;
            float v = acc[i][jj] + bias[col];
            if (RELU) v = fmaxf(v, 0.f);
            C[(size_t)row * Nout + col] = v;
        }
    }
}

// ============================================================================
// G precompute on HMMA: G = fp16( xp @ Wih_p^T + bias_p ), hi/lo split A.
// CTA = 64 nodes, 8 warps: warp = 16 rows (rg=w&3) x 256 cols (ch=w>>2, nb=4ch..+3)
// SMEM: Wih 128KB @0, Ahi 16KB @131072, Alo 16KB @147456, bias 2KB @163840
// ============================================================================
#define GP_WIH  0
#define GP_AHI  131072
#define GP_ALO  147456
#define GP_BIAS 163840
#define GP_SMEM 165888

__global__ __launch_bounds__(256, 1) void gprep_mma(
    const float* __restrict__ xp, __half2* __restrict__ G2)
{
    extern __shared__ char sm[];
    __half* wih = (__half*)(sm + GP_WIH);
    __half* ahi = (__half*)(sm + GP_AHI);
    __half* alo = (__half*)(sm + GP_ALO);
    float*  bs  = (float*)(sm + GP_BIAS);
    const uint32_t wih_u = smem_u32(wih), ahi_u = smem_u32(ahi), alo_u = smem_u32(alo);
    const int tid = threadIdx.x, w = tid >> 5, lane = tid & 31;
    const int rg = w & 3, ch = w >> 2;
    const int q = lane & 3, r = lane >> 2;
    const int nodeBase = blockIdx.x * 64;

    // stage Wih_p fp16 swizzled: row p, chunk c(16B) -> phys c ^ (p&7)
    for (int idx = tid; idx < 8192; idx += 256) {
        int row = idx >> 4, chk = idx & 15;
        int phys = chk ^ (row & 7);
        *(uint4*)(wih + row * 128 + phys * 8) = *(const uint4*)(g_Wihp + row * 128 + chk * 8);
    }
    for (int i = tid; i < F4; i += 256) bs[i] = g_biasp[i];
    // stage A hi/lo
    for (int idx = tid; idx < 1024; idx += 256) {
        int row = idx >> 4, chk = idx & 15;
        int node = nodeBase + row;
        float v[8];
        if (node < NN) {
            float4 v0 = *(const float4*)(xp + (size_t)node * FF + chk * 8);
            float4 v1 = *(const float4*)(xp + (size_t)node * FF + chk * 8 + 4);
            v[0]=v0.x; v[1]=v0.y; v[2]=v0.z; v[3]=v0.w; v[4]=v1.x; v[5]=v1.y; v[6]=v1.z; v[7]=v1.w;
        } else {
            #pragma unroll
            for (int e = 0; e < 8; e++) v[e] = 0.f;
        }
        __half2 hh[4], hl[4];
        #pragma unroll
        for (int e = 0; e < 4; e++) {
            __half h0 = __float2half_rn(v[2*e]), h1 = __float2half_rn(v[2*e+1]);
            hh[e] = __halves2half2(h0, h1);
            hl[e] = __halves2half2(__float2half_rn(v[2*e] - __half2float(h0)),
                                   __float2half_rn(v[2*e+1] - __half2float(h1)));
        }
        int phys = chk ^ (row & 7);
        *(uint4*)(ahi + row * 128 + phys * 8) = *(const uint4*)hh;
        *(uint4*)(alo + row * 128 + phys * 8) = *(const uint4*)hl;
    }
    __syncthreads();

    // A fragments (whole K), hi and lo
    uint32_t Ah[8][4], Al[8][4];
    {
        int rowb = rg * 16 + (lane & 7) + ((lane >> 3) & 1) * 8;
        #pragma unroll
        for (int kt = 0; kt < 8; kt++) {
            int chk = 2 * kt + (lane >> 4);
            int phys = chk ^ (rowb & 7);
            ldsm4(ahi_u + rowb * 256 + phys * 16, Ah[kt]);
            ldsm4(alo_u + rowb * 256 + phys * 16, Al[kt]);
        }
    }

    #pragma unroll
    for (int j = 0; j < 4; j++) {
        const int nb = ch * 4 + j;
        #pragma unroll
        for (int a = 0; a < 4; a++) {
            float acc[2][4] = {};
            #pragma unroll
            for (int sp = 0; sp < 2; sp++) {
                int s = 2 * a + sp;
                int rowb = nb * 64 + s * 8 + (lane & 7);
                uint32_t b[4][4];
                #pragma unroll
                for (int ktp = 0; ktp < 4; ktp++) {
                    int chk = 4 * ktp + (lane >> 3);
                    int phys = chk ^ (rowb & 7);
                    ldsm4(wih_u + rowb * 256 + phys * 16, b[ktp]);
                }
                #pragma unroll
                for (int kt = 0; kt < 8; kt++) {
                    uint32_t b0 = b[kt >> 1][(kt & 1) * 2], b1 = b[kt >> 1][(kt & 1) * 2 + 1];
                    mma16816(acc[sp], Ah[kt], b0, b1);
                    mma16816(acc[sp], Al[kt], b0, b1);
                }
            }
            int colif = nb * 64 + 16 * a + 2 * q;
            float bi = bs[colif], bf = bs[colif + 1], bg = bs[colif + 8], bo = bs[colif + 9];
            #pragma unroll
            for (int rp = 0; rp < 2; rp++) {
                int nl = rg * 16 + r + rp * 8;
                int node = nodeBase + nl;
                if (node < NN) {
                    float iv = acc[0][rp * 2 + 0] + bi;
                    float fv = acc[0][rp * 2 + 1] + bf;
                    float gv = acc[1][rp * 2 + 0] + bg;
                    float ov = acc[1][rp * 2 + 1] + bo;
                    size_t base = (size_t)node * 256 + nb * 32 + a * 8 + q;
                    G2[base]     = __floats2half2_rn(iv, fv);
                    G2[base + 4] = __floats2half2_rn(gv, ov);
                }
            }
        }
    }
}

// ============================================================================
// LSTM aggregation on HMMA.
// CTA = 128 nodes, 8 warps: warp = 32 rows (rg=w&3) x 256 cols (ch=w>>2).
// Per step: D = h_{t-1} @ Whh_p^T via mma.sync (skip t=0), + gathered G,
// elementwise LSTM; h fp16 -> SMEM (ldmatrix layout), c fp32 SMEM.
// SMEM: Whh 128KB @0, h 32KB @131072, c 67584B @163840  => 231424 B
// ============================================================================
#define LS_WHH  0
#define LS_H    131072
#define LS_C    163840
#define LS_SMEM (163840 + 128 * 132 * 4)

__global__ __launch_bounds__(256, 1) void lstm_mma(
    const __half2* __restrict__ G2, const int* __restrict__ esrc,
    float* __restrict__ aggr)
{
    extern __shared__ char sm[];
    __half* whh = (__half*)(sm + LS_WHH);
    __half* hb  = (__half*)(sm + LS_H);
    float*  cs  = (float*)(sm + LS_C);
    const uint32_t whh_u = smem_u32(whh), hb_u = smem_u32(hb);
    const int tid = threadIdx.x, w = tid >> 5, lane = tid & 31;
    const int rg = w & 3, ch = w >> 2;
    const int q = lane & 3, r = lane >> 2;
    const int nodeBase = blockIdx.x * 128;

    // stage Whh_p fp16 swizzled
    for (int idx = tid; idx < 8192; idx += 256) {
        int row = idx >> 4, chk = idx & 15;
        int phys = chk ^ (row & 7);
        *(uint4*)(whh + row * 128 + phys * 8) = *(const uint4*)(g_Whhp + row * 128 + chk * 8);
    }

    uint32_t Af[2][8][4];
    int srcs[4];

    for (int t = 0; t < 16; t++) {
        if (t > 0) {
            __syncthreads();   // h(t-1) writes complete (also covers Whh staging at t=1)
            #pragma unroll
            for (int mt2 = 0; mt2 < 2; mt2++) {
                int rowb = rg * 32 + mt2 * 16 + (lane & 7) + ((lane >> 3) & 1) * 8;
                #pragma unroll
                for (int kt = 0; kt < 8; kt++) {
                    int chk = 2 * kt + (lane >> 4);
                    int phys = chk ^ (rowb & 7);
                    ldsm4(hb_u + rowb * 256 + phys * 16, Af[mt2][kt]);
                }
            }
            __syncthreads();   // all A reads done before anyone overwrites h
        }
        #pragma unroll
        for (int mt2 = 0; mt2 < 2; mt2++)
            #pragma unroll
            for (int rp = 0; rp < 2; rp++) {
                int node = nodeBase + rg * 32 + mt2 * 16 + r + rp * 8;
                srcs[mt2 * 2 + rp] = (node < NN) ? __ldg(esrc + (size_t)node * DD + t) : 0;
            }

        #pragma unroll
        for (int j = 0; j < 4; j++) {
            const int nb = ch * 4 + j;
            #pragma unroll
            for (int a = 0; a < 4; a++) {
                // prefetch gathered G for this (nb,a) — overlaps the MMAs below
                __half2 gif[2][2], ggo[2][2];
                #pragma unroll
                for (int mt2 = 0; mt2 < 2; mt2++)
                    #pragma unroll
                    for (int rp = 0; rp < 2; rp++) {
                        size_t base = (size_t)srcs[mt2 * 2 + rp] * 256 + nb * 32 + a * 8 + q;
                        gif[mt2][rp] = __ldg(G2 + base);
                        ggo[mt2][rp] = __ldg(G2 + base + 4);
                    }
                float acc[2][2][4] = {};
                if (t > 0) {
                    #pragma unroll
                    for (int sp = 0; sp < 2; sp++) {
                        int s = 2 * a + sp;
                        int rowb = nb * 64 + s * 8 + (lane & 7);
                        uint32_t b[4][4];
                        #pragma unroll
                        for (int ktp = 0; ktp < 4; ktp++) {
                            int chk = 4 * ktp + (lane >> 3);
                            int phys = chk ^ (rowb & 7);
                            ldsm4(whh_u + rowb * 256 + phys * 16, b[ktp]);
                        }
                        #pragma unroll
                        for (int mt2 = 0; mt2 < 2; mt2++)
                            #pragma unroll
                            for (int kt = 0; kt < 8; kt++)
                                mma16816(acc[sp][mt2], Af[mt2][kt],
                                         b[kt >> 1][(kt & 1) * 2], b[kt >> 1][(kt & 1) * 2 + 1]);
                    }
                }
                const int u = nb * 16 + 4 * a + q;
                #pragma unroll
                for (int mt2 = 0; mt2 < 2; mt2++)
                    #pragma unroll
                    for (int rp = 0; rp < 2; rp++) {
                        int nl = rg * 32 + mt2 * 16 + r + rp * 8;
                        float iv = acc[0][mt2][rp * 2 + 0] + __low2float(gif[mt2][rp]);
                        float fv = acc[0][mt2][rp * 2 + 1] + __high2float(gif[mt2][rp]);
                        float gv = acc[1][mt2][rp * 2 + 0] + __low2float(ggo[mt2][rp]);
                        float ov = acc[1][mt2][rp * 2 + 1] + __high2float(ggo[mt2][rp]);
                        float cold = (t > 0) ? cs[nl * 132 + u] : 0.f;
                        float cn = sigf(fv) * cold + sigf(iv) * tanha(gv);
                        cs[nl * 132 + u] = cn;
                        float h = sigf(ov) * tanha(cn);
                        if (t < 15) {
                            int phys = (u >> 3) ^ (nl & 7);
                            hb[nl * 128 + phys * 8 + (u & 7)] = __float2half_rn(h);
                        } else {
                            int node = nodeBase + nl;
                            if (node < NN) aggr[(size_t)node * FF + u] = h;
                        }
                    }
            }
        }
    }
}

// ============================================================================
extern "C" void kernel_launch(void* const* d_in, const int* in_sizes, int n_in,
                              void* d_out, int out_size)
{
    const float* x    = (const float*)d_in[0];
    const int*   esrc = (const int*)d_in[1];
    // d_in[2..7] = dead MLP branch
    const float* Wp1  = (const float*)d_in[8];
    const float* bp1  = (const float*)d_in[9];
    const float* Wih1 = (const float*)d_in[10];
    const float* Whh1 = (const float*)d_in[11];
    const float* bih1 = (const float*)d_in[12];
    const float* bhh1 = (const float*)d_in[13];
    const float* Wl1  = (const float*)d_in[14];
    const float* bl1  = (const float*)d_in[15];
    const float* Wr1  = (const float*)d_in[16];
    const float* Wp2  = (const float*)d_in[17];
    const float* bp2  = (const float*)d_in[18];
    const float* Wih2 = (const float*)d_in[19];
    const float* Whh2 = (const float*)d_in[20];
    const float* bih2 = (const float*)d_in[21];
    const float* bhh2 = (const float*)d_in[22];
    const float* Wl2  = (const float*)d_in[23];
    const float* bl2  = (const float*)d_in[24];
    const float* Wr2  = (const float*)d_in[25];
    float* out = (float*)d_out;

    float *xp, *aggr, *h1;
    __half* G;
    cudaGetSymbolAddress((void**)&xp,   g_xp);
    cudaGetSymbolAddress((void**)&G,    g_G);
    cudaGetSymbolAddress((void**)&aggr, g_aggr);
    cudaGetSymbolAddress((void**)&h1,   g_h1);

    cudaFuncSetAttribute(gprep_mma, cudaFuncAttributeMaxDynamicSharedMemorySize, GP_SMEM);
    cudaFuncSetAttribute(lstm_mma,  cudaFuncAttributeMaxDynamicSharedMemorySize, LS_SMEM);

    dim3 thr(256);
    const int mblk64  = (NN + 63) / 64;     // 782
    const int mblk128 = (NN + 127) / 128;   // 391
    dim3 gN128(2, mblk64);
    dim3 gN40(1, mblk64);

    // ---------- layer 1 ----------
    prep_permute<<<F4, 128>>>(Wih1, Whh1, bih1, bhh1);
    gemm_kernel<true, false><<<gN128, thr>>>(x, Wp1, nullptr, nullptr, bp1, xp, NN, FF);
    gprep_mma<<<mblk64, thr, GP_SMEM>>>(xp, (__half2*)G);
    lstm_mma<<<mblk128, thr, LS_SMEM>>>((const __half2*)G, esrc, aggr);
    gemm_kernel<true, true><<<gN128, thr>>>(aggr, Wl1, x, Wr1, bl1, h1, NN, FF);

    // ---------- layer 2 ----------
    prep_permute<<<F4, 128>>>(Wih2, Whh2, bih2, bhh2);
    gemm_kernel<true, false><<<gN128, thr>>>(h1, Wp2, nullptr, nullptr, bp2, xp, NN, FF);
    gprep_mma<<<mblk64, thr, GP_SMEM>>>(xp, (__half2*)G);
    lstm_mma<<<mblk128, thr, LS_SMEM>>>((const __half2*)G, esrc, aggr);
    gemm_kernel<false, true><<<gN40, thr>>>(aggr, Wl2, h1, Wr2, bl2, out, NN, CCLS);
}

// round 4
// speedup vs baseline: 6.8781x; 1.2693x over previous
#include <cuda_runtime.h>
#include <cuda_fp16.h>
#include <math.h>
#include <stdint.h>

#define NN   50000
#define DD   16
#define FF   128
#define F4   512
#define CCLS 40

// ---- scratch (device globals: allocation-free rule) ----
__device__ float  g_xp[(size_t)NN * FF];     // projected features fp32
__device__ __half g_G[(size_t)NN * F4];      // permuted gate preacts, fp16 (51MB, L2-resident)
__device__ float  g_aggr[(size_t)NN * FF];   // LSTM output
__device__ float  g_h1[(size_t)NN * FF];     // layer-1 output
__device__ __half g_Whhp[F4 * FF];           // permuted Whh fp16
__device__ __half g_Wihp[F4 * FF];           // permuted Wih fp16
__device__ float  g_biasp[F4];               // permuted bih+bhh

// ============================================================================
// helpers
// ============================================================================
__device__ __forceinline__ uint32_t smem_u32(const void* p) {
    uint32_t a;
    asm("{ .reg .u64 t; cvta.to.shared.u64 t, %1; cvt.u32.u64 %0, t; }" : "=r"(a) : "l"(p));
    return a;
}
__device__ __forceinline__ void ldsm4(uint32_t addr, uint32_t r[4]) {
    asm volatile("ldmatrix.sync.aligned.m8n8.x4.shared.b16 {%0,%1,%2,%3}, [%4];"
        : "=r"(r[0]), "=r"(r[1]), "=r"(r[2]), "=r"(r[3]) : "r"(addr));
}
__device__ __forceinline__ void mma16816(float d[4], const uint32_t a[4], uint32_t b0, uint32_t b1) {
    asm volatile("mma.sync.aligned.m16n8k16.row.col.f32.f16.f16.f32 "
        "{%0,%1,%2,%3},{%4,%5,%6,%7},{%8,%9},{%0,%1,%2,%3};"
        : "+f"(d[0]), "+f"(d[1]), "+f"(d[2]), "+f"(d[3])
        : "r"(a[0]), "r"(a[1]), "r"(a[2]), "r"(a[3]), "r"(b0), "r"(b1));
}
__device__ __forceinline__ float tna(float x) { float y; asm("tanh.approx.f32 %0, %1;" : "=f"(y) : "f"(x)); return y; }
__device__ __forceinline__ float sigf(float x) { return 0.5f + 0.5f * tna(0.5f * x); }
#define BARG(id) asm volatile("bar.sync %0, 128;" :: "r"(id) : "memory")

// ============================================================================
// Gate-interleave permutation (see R3 comment): thread-local gate quads.
// ============================================================================
__global__ void prep_permute(const float* __restrict__ Wih, const float* __restrict__ Whh,
                             const float* __restrict__ bih, const float* __restrict__ bhh) {
    int p = blockIdx.x;                 // 0..511 permuted row
    int c = p & 63;
    int nb = p >> 6;
    int c15 = c & 15;
    int g = 2 * ((c15 >> 3) & 1) + (c15 & 1);
    int q = (c15 & 7) >> 1;
    int a = (c >> 4) & 3;
    int u = nb * 16 + 4 * a + q;
    int srow = g * FF + u;              // torch gate order i,f,g,o blocks of 128
    for (int k = threadIdx.x; k < FF; k += blockDim.x) {
        g_Wihp[p * FF + k] = __float2half_rn(Wih[srow * FF + k]);
        g_Whhp[p * FF + k] = __float2half_rn(Whh[srow * FF + k]);
    }
    if (threadIdx.x == 0) g_biasp[p] = bih[srow] + bhh[srow];
}

// ============================================================================
// fp32 SIMT GEMM (small layers): C = act( A@W^T (+ A2@W2^T) + b )
// ============================================================================
template<bool RELU, bool DUAL>
__global__ __launch_bounds__(256) void gemm_kernel(
    const float* __restrict__ A,  const float* __restrict__ W,
    const float* __restrict__ A2, const float* __restrict__ W2,
    const float* __restrict__ bias,
    float* __restrict__ C, int M, int Nout)
{
    __shared__ float As[16][65];
    __shared__ float Ws[16][65];
    const int tid = threadIdx.x;
    const int tx = tid & 15, ty = tid >> 4;
    const int rowBase = blockIdx.y * 64;
    const int colBase = blockIdx.x * 64;
    const int lk = tid & 15, lr = tid >> 4;
    float acc[4][4] = {};
    const int npass = DUAL ? 2 : 1;
    for (int p = 0; p < npass; p++) {
        const float* Ap = p ? A2 : A;
        const float* Wp = p ? W2 : W;
        for (int k0 = 0; k0 < FF; k0 += 16) {
            #pragma unroll
            for (int rr = 0; rr < 4; rr++) {
                int row = rowBase + lr + rr * 16;
                As[lk][lr + rr * 16] = (row < M) ? Ap[(size_t)row * FF + k0 + lk] : 0.f;
                int wr = colBase + lr + rr * 16;
                Ws[lk][lr + rr * 16] = (wr < Nout) ? Wp[(size_t)wr * FF + k0 + lk] : 0.f;
            }
            __syncthreads();
            #pragma unroll
            for (int kk = 0; kk < 16; kk++) {
                float av[4], bv[4];
                #pragma unroll
                for (int i = 0; i < 4; i++) av[i] = As[kk][ty * 4 + i];
                #pragma unroll
                for (int jj = 0; jj < 4; jj++) bv[jj] = Ws[kk][tx * 4 + jj];
                #pragma unroll
                for (int i = 0; i < 4; i++)
                    #pragma unroll
                    for (int jj = 0; jj < 4; jj++)
                        acc[i][jj] = fmaf(av[i], bv[jj], acc[i][jj]);
            }
            __syncthreads();
        }
    }
    #pragma unroll
    for (int i = 0; i < 4; i++) {
        int row = rowBase + ty * 4 + i;
        if (row >= M) continue;
        #pragma unroll
        for (int jj = 0; jj < 4; jj++) {
            int col = colBase + tx * 4 + jj;
            if (col >= Nout) continue;
            float v = acc[i][jj] + bias[col];
            if (RELU) v = fmaxf(v, 0.f);
            C[(size_t)row * Nout + col] = v;
        }
    }
}

// ============================================================================
// G precompute on HMMA: G = fp16( xp @ Wih_p^T + bias_p ), hi/lo split A.
// CTA = 64 nodes, 8 warps: warp = 16 rows (rg=w&3) x 256 cols (ch=w>>2)
// SMEM: Wih 128KB @0, Ahi 16KB @131072, Alo 16KB @147456, bias 2KB @163840
// ============================================================================
#define GP_WIH  0
#define GP_AHI  131072
#define GP_ALO  147456
#define GP_BIAS 163840
#define GP_SMEM 165888

__global__ __launch_bounds__(256, 1) void gprep_mma(
    const float* __restrict__ xp, __half2* __restrict__ G2)
{
    extern __shared__ char sm[];
    __half* wih = (__half*)(sm + GP_WIH);
    __half* ahi = (__half*)(sm + GP_AHI);
    __half* alo = (__half*)(sm + GP_ALO);
    float*  bs  = (float*)(sm + GP_BIAS);
    const uint32_t wih_u = smem_u32(wih), ahi_u = smem_u32(ahi), alo_u = smem_u32(alo);
    const int tid = threadIdx.x, w = tid >> 5, lane = tid & 31;
    const int rg = w & 3, ch = w >> 2;
    const int q = lane & 3, r = lane >> 2;
    const int nodeBase = blockIdx.x * 64;

    for (int idx = tid; idx < 8192; idx += 256) {
        int row = idx >> 4, chk = idx & 15;
        int phys = chk ^ (row & 7);
        *(uint4*)(wih + row * 128 + phys * 8) = *(const uint4*)(g_Wihp + row * 128 + chk * 8);
    }
    for (int i = tid; i < F4; i += 256) bs[i] = g_biasp[i];
    for (int idx = tid; idx < 1024; idx += 256) {
        int row = idx >> 4, chk = idx & 15;
        int node = nodeBase + row;
        float v[8];
        if (node < NN) {
            float4 v0 = *(const float4*)(xp + (size_t)node * FF + chk * 8);
            float4 v1 = *(const float4*)(xp + (size_t)node * FF + chk * 8 + 4);
            v[0]=v0.x; v[1]=v0.y; v[2]=v0.z; v[3]=v0.w; v[4]=v1.x; v[5]=v1.y; v[6]=v1.z; v[7]=v1.w;
        } else {
            #pragma unroll
            for (int e = 0; e < 8; e++) v[e] = 0.f;
        }
        __half2 hh[4], hl[4];
        #pragma unroll
        for (int e = 0; e < 4; e++) {
            __half h0 = __float2half_rn(v[2*e]), h1 = __float2half_rn(v[2*e+1]);
            hh[e] = __halves2half2(h0, h1);
            hl[e] = __halves2half2(__float2half_rn(v[2*e] - __half2float(h0)),
                                   __float2half_rn(v[2*e+1] - __half2float(h1)));
        }
        int phys = chk ^ (row & 7);
        *(uint4*)(ahi + row * 128 + phys * 8) = *(const uint4*)hh;
        *(uint4*)(alo + row * 128 + phys * 8) = *(const uint4*)hl;
    }
    __syncthreads();

    uint32_t Ah[8][4], Al[8][4];
    {
        int rowb = rg * 16 + (lane & 7) + ((lane >> 3) & 1) * 8;
        #pragma unroll
        for (int kt = 0; kt < 8; kt++) {
            int chk = 2 * kt + (lane >> 4);
            int phys = chk ^ (rowb & 7);
            ldsm4(ahi_u + rowb * 256 + phys * 16, Ah[kt]);
            ldsm4(alo_u + rowb * 256 + phys * 16, Al[kt]);
        }
    }

    #pragma unroll
    for (int j = 0; j < 4; j++) {
        const int nb = ch * 4 + j;
        #pragma unroll
        for (int a = 0; a < 4; a++) {
            float acc[2][4] = {};
            #pragma unroll
            for (int sp = 0; sp < 2; sp++) {
                int s = 2 * a + sp;
                int rowb = nb * 64 + s * 8 + (lane & 7);
                uint32_t b[4][4];
                #pragma unroll
                for (int ktp = 0; ktp < 4; ktp++) {
                    int chk = 4 * ktp + (lane >> 3);
                    int phys = chk ^ (rowb & 7);
                    ldsm4(wih_u + rowb * 256 + phys * 16, b[ktp]);
                }
                #pragma unroll
                for (int kt = 0; kt < 8; kt++) {
                    uint32_t b0 = b[kt >> 1][(kt & 1) * 2], b1 = b[kt >> 1][(kt & 1) * 2 + 1];
                    mma16816(acc[sp], Ah[kt], b0, b1);
                    mma16816(acc[sp], Al[kt], b0, b1);
                }
            }
            int colif = nb * 64 + 16 * a + 2 * q;
            float bi = bs[colif], bf = bs[colif + 1], bg = bs[colif + 8], bo = bs[colif + 9];
            #pragma unroll
            for (int rp = 0; rp < 2; rp++) {
                int nl = rg * 16 + r + rp * 8;
                int node = nodeBase + nl;
                if (node < NN) {
                    float iv = acc[0][rp * 2 + 0] + bi;
                    float fv = acc[0][rp * 2 + 1] + bf;
                    float gv = acc[1][rp * 2 + 0] + bg;
                    float ov = acc[1][rp * 2 + 1] + bo;
                    size_t base = (size_t)node * 256 + nb * 32 + a * 8 + q;
                    G2[base]     = __floats2half2_rn(iv, fv);
                    G2[base + 4] = __floats2half2_rn(gv, ov);
                }
            }
        }
    }
}

// ============================================================================
// LSTM aggregation on HMMA — v2: 512 threads / 16 warps, row-group named
// barriers, all-approx activations.
// Warp (rg=w&3, ch=w>>2): rows rg*32..+32 (2 m-tiles), gate cols ch*128..+128
// (nb = ch*2, ch*2+1) -> units ch*32..+32 for its rows.
// A-fragments (h) for row-group rg depend only on warps with same rg ->
// bar.sync (rg+1), 128 instead of __syncthreads.
// SMEM: Whh 128KB @0, h 32KB @131072, c @163840 (128x132 f32) => 231424 B
// ============================================================================
#define LS_WHH  0
#define LS_H    131072
#define LS_C    163840
#define LS_SMEM (163840 + 128 * 132 * 4)

__global__ __launch_bounds__(512, 1) void lstm_mma(
    const __half2* __restrict__ G2, const int* __restrict__ esrc,
    float* __restrict__ aggr)
{
    extern __shared__ char sm[];
    __half* whh = (__half*)(sm + LS_WHH);
    __half* hb  = (__half*)(sm + LS_H);
    float*  cs  = (float*)(sm + LS_C);
    const uint32_t whh_u = smem_u32(whh), hb_u = smem_u32(hb);
    const int tid = threadIdx.x, w = tid >> 5, lane = tid & 31;
    const int rg = w & 3, ch = w >> 2;          // ch in 0..3
    const int q = lane & 3, r = lane >> 2;
    const int nodeBase = blockIdx.x * 128;

    // stage Whh_p fp16 swizzled (512 threads)
    for (int idx = tid; idx < 8192; idx += 512) {
        int row = idx >> 4, chk = idx & 15;
        int phys = chk ^ (row & 7);
        *(uint4*)(whh + row * 128 + phys * 8) = *(const uint4*)(g_Whhp + row * 128 + chk * 8);
    }
    __syncthreads();

    uint32_t Af[2][8][4];
    int srcs[4];

    for (int t = 0; t < 16; t++) {
        if (t > 0) {
            BARG(rg + 1);   // h(t-1) writes by this row-group's 4 warps complete
            #pragma unroll
            for (int mt2 = 0; mt2 < 2; mt2++) {
                int rowb = rg * 32 + mt2 * 16 + (lane & 7) + ((lane >> 3) & 1) * 8;
                #pragma unroll
                for (int kt = 0; kt < 8; kt++) {
                    int chk = 2 * kt + (lane >> 4);
                    int phys = chk ^ (rowb & 7);
                    ldsm4(hb_u + rowb * 256 + phys * 16, Af[mt2][kt]);
                }
            }
            BARG(rg + 1);   // A reads done before anyone in group overwrites h
        }
        #pragma unroll
        for (int mt2 = 0; mt2 < 2; mt2++)
            #pragma unroll
            for (int rp = 0; rp < 2; rp++) {
                int node = nodeBase + rg * 32 + mt2 * 16 + r + rp * 8;
                srcs[mt2 * 2 + rp] = (node < NN) ? __ldg(esrc + (size_t)node * DD + t) : 0;
            }

        #pragma unroll
        for (int j = 0; j < 2; j++) {
            const int nb = ch * 2 + j;
            #pragma unroll
            for (int a = 0; a < 4; a++) {
                // prefetch gathered G (overlaps the MMAs below)
                __half2 gif[2][2], ggo[2][2];
                #pragma unroll
                for (int mt2 = 0; mt2 < 2; mt2++)
                    #pragma unroll
                    for (int rp = 0; rp < 2; rp++) {
                        size_t base = (size_t)srcs[mt2 * 2 + rp] * 256 + nb * 32 + a * 8 + q;
                        gif[mt2][rp] = __ldg(G2 + base);
                        ggo[mt2][rp] = __ldg(G2 + base + 4);
                    }
                float acc[2][2][4] = {};
                if (t > 0) {
                    #pragma unroll
                    for (int sp = 0; sp < 2; sp++) {
                        int s = 2 * a + sp;
                        int rowb = nb * 64 + s * 8 + (lane & 7);
                        uint32_t b[4][4];
                        #pragma unroll
                        for (int ktp = 0; ktp < 4; ktp++) {
                            int chk = 4 * ktp + (lane >> 3);
                            int phys = chk ^ (rowb & 7);
                            ldsm4(whh_u + rowb * 256 + phys * 16, b[ktp]);
                        }
                        #pragma unroll
                        for (int mt2 = 0; mt2 < 2; mt2++)
                            #pragma unroll
                            for (int kt = 0; kt < 8; kt++)
                                mma16816(acc[sp][mt2], Af[mt2][kt],
                                         b[kt >> 1][(kt & 1) * 2], b[kt >> 1][(kt & 1) * 2 + 1]);
                    }
                }
                const int u = nb * 16 + 4 * a + q;
                #pragma unroll
                for (int mt2 = 0; mt2 < 2; mt2++)
                    #pragma unroll
                    for (int rp = 0; rp < 2; rp++) {
                        int nl = rg * 32 + mt2 * 16 + r + rp * 8;
                        float iv = acc[0][mt2][rp * 2 + 0] + __low2float(gif[mt2][rp]);
                        float fv = acc[0][mt2][rp * 2 + 1] + __high2float(gif[mt2][rp]);
                        float gv = acc[1][mt2][rp * 2 + 0] + __low2float(ggo[mt2][rp]);
                        float ov = acc[1][mt2][rp * 2 + 1] + __high2float(ggo[mt2][rp]);
                        float cold = (t > 0) ? cs[nl * 132 + u] : 0.f;
                        float cn = sigf(fv) * cold + sigf(iv) * tna(gv);
                        cs[nl * 132 + u] = cn;
                        float h = sigf(ov) * tna(cn);
                        if (t < 15) {
                            int phys = (u >> 3) ^ (nl & 7);
                            hb[nl * 128 + phys * 8 + (u & 7)] = __float2half_rn(h);
                        } else {
                            int node = nodeBase + nl;
                            if (node < NN) aggr[(size_t)node * FF + u] = h;
                        }
                    }
            }
        }
    }
}

// ============================================================================
extern "C" void kernel_launch(void* const* d_in, const int* in_sizes, int n_in,
                              void* d_out, int out_size)
{
    const float* x    = (const float*)d_in[0];
    const int*   esrc = (const int*)d_in[1];
    // d_in[2..7] = dead MLP branch
    const float* Wp1  = (const float*)d_in[8];
    const float* bp1  = (const float*)d_in[9];
    const float* Wih1 = (const float*)d_in[10];
    const float* Whh1 = (const float*)d_in[11];
    const float* bih1 = (const float*)d_in[12];
    const float* bhh1 = (const float*)d_in[13];
    const float* Wl1  = (const float*)d_in[14];
    const float* bl1  = (const float*)d_in[15];
    const float* Wr1  = (const float*)d_in[16];
    const float* Wp2  = (const float*)d_in[17];
    const float* bp2  = (const float*)d_in[18];
    const float* Wih2 = (const float*)d_in[19];
    const float* Whh2 = (const float*)d_in[20];
    const float* bih2 = (const float*)d_in[21];
    const float* bhh2 = (const float*)d_in[22];
    const float* Wl2  = (const float*)d_in[23];
    const float* bl2  = (const float*)d_in[24];
    const float* Wr2  = (const float*)d_in[25];
    float* out = (float*)d_out;

    float *xp, *aggr, *h1;
    __half* G;
    cudaGetSymbolAddress((void**)&xp,   g_xp);
    cudaGetSymbolAddress((void**)&G,    g_G);
    cudaGetSymbolAddress((void**)&aggr, g_aggr);
    cudaGetSymbolAddress((void**)&h1,   g_h1);

    cudaFuncSetAttribute(gprep_mma, cudaFuncAttributeMaxDynamicSharedMemorySize, GP_SMEM);
    cudaFuncSetAttribute(lstm_mma,  cudaFuncAttributeMaxDynamicSharedMemorySize, LS_SMEM);

    const int mblk64  = (NN + 63) / 64;     // 782
    const int mblk128 = (NN + 127) / 128;   // 391
    dim3 gN128(2, mblk64);
    dim3 gN40(1, mblk64);

    // ---------- layer 1 ----------
    prep_permute<<<F4, 128>>>(Wih1, Whh1, bih1, bhh1);
    gemm_kernel<true, false><<<gN128, 256>>>(x, Wp1, nullptr, nullptr, bp1, xp, NN, FF);
    gprep_mma<<<mblk64, 256, GP_SMEM>>>(xp, (__half2*)G);
    lstm_mma<<<mblk128, 512, LS_SMEM>>>((const __half2*)G, esrc, aggr);
    gemm_kernel<true, true><<<gN128, 256>>>(aggr, Wl1, x, Wr1, bl1, h1, NN, FF);

    // ---------- layer 2 ----------
    prep_permute<<<F4, 128>>>(Wih2, Whh2, bih2, bhh2);
    gemm_kernel<true, false><<<gN128, 256>>>(h1, Wp2, nullptr, nullptr, bp2, xp, NN, FF);
    gprep_mma<<<mblk64, 256, GP_SMEM>>>(xp, (__half2*)G);
    lstm_mma<<<mblk128, 512, LS_SMEM>>>((const __half2*)G, esrc, aggr);
    gemm_kernel<false, true><<<gN40, 256>>>(aggr, Wl2, h1, Wr2, bl2, out, NN, CCLS);
}